// round 11
// baseline (speedup 1.0000x reference)
#include <cuda_runtime.h>
#include <cstdint>

// SparseStateAggregator: 8-CTA cluster per batch, 128 cols per CTA in SMEM.
// Per token: parallel partial dots -> DSMEM stores (disjoint addrs) ->
// ONE aggregated arrive per peer (7 total, distinct mbarriers) ->
// all 8 warps redundantly compute the identical decision from registers ->
// each warp updates its slice. 2 syncthreads/token, depth-2 buffers.

#define D_DIM   1024
#define M_ST    64
#define RANKS   8
#define COLS    128
#define TPB     256
#define THRESH_F 0.9f
#define EPS_F   1e-12f

// ---- shared memory layout (bytes) ----
#define OFF_MBAR   0       // 2 x u64 mbarriers (token-parity double buffer)
#define OFF_SQ4    16      // 4 floats: per-warp sq partials of updated cent row
#define OFF_KSH    32      // 2 x 128 floats (ping-pong token keys)
#define OFF_VSH    1056    // 2 x 128 floats (ping-pong token values)
#define OFF_RECV   2080    // float recv[2][8][68]: 0..63 dots, 64 |k|^2, 65 cn2 partial
#define OFF_CENT   6432    // 64*128 floats
#define OFF_STAT   39200   // 64*128 floats
#define SMEM_BYTES 71968

static __device__ __forceinline__ uint32_t smem_u32(const void* p) {
    uint32_t a;
    asm("{ .reg .u64 t; cvta.to.shared.u64 t, %1; cvt.u32.u64 %0, t; }"
        : "=r"(a) : "l"(p));
    return a;
}
static __device__ __forceinline__ uint32_t mapa_rank(uint32_t addr, uint32_t rank) {
    uint32_t ra;
    asm("mapa.shared::cluster.u32 %0, %1, %2;" : "=r"(ra) : "r"(addr), "r"(rank));
    return ra;
}
static __device__ __forceinline__ void st_dsmem(uint32_t addr, float v) {
    asm volatile("st.shared::cluster.f32 [%0], %1;" :: "r"(addr), "f"(v) : "memory");
}
static __device__ __forceinline__ void mbar_init(uint32_t addr, uint32_t cnt) {
    asm volatile("mbarrier.init.shared.b64 [%0], %1;" :: "r"(addr), "r"(cnt) : "memory");
}
static __device__ __forceinline__ void mbar_arrive_remote(uint32_t local_mbar, uint32_t rank) {
    uint32_t ra = mapa_rank(local_mbar, rank);
    asm volatile("mbarrier.arrive.release.cluster.shared::cluster.b64 _, [%0];"
                 :: "r"(ra) : "memory");
}
static __device__ __forceinline__ void mbar_wait_cluster(uint32_t mbar, uint32_t parity) {
    asm volatile(
        "{\n\t"
        ".reg .pred P1;\n\t"
        "LAB_WAIT_%=:\n\t"
        "mbarrier.try_wait.parity.acquire.cluster.shared::cta.b64 P1, [%0], %1;\n\t"
        "@!P1 bra LAB_WAIT_%=;\n\t"
        "}\n"
        :: "r"(mbar), "r"(parity) : "memory");
}
static __device__ __forceinline__ void cluster_sync_all() {
    asm volatile("barrier.cluster.arrive.aligned;" ::: "memory");
    asm volatile("barrier.cluster.wait.aligned;" ::: "memory");
}

__global__ void __cluster_dims__(RANKS, 1, 1) __launch_bounds__(TPB, 1)
sparse_agg_kernel(const float* __restrict__ keys,
                  const float* __restrict__ values,
                  float* __restrict__ out, int S)
{
    extern __shared__ unsigned char sm[];
    const uint32_t sbase = smem_u32(sm);

    const int tid  = threadIdx.x;
    const int wid  = tid >> 5;
    const int lane = tid & 31;
    const int rank = blockIdx.x & (RANKS - 1);
    const int b    = blockIdx.x >> 3;
    const int c0   = rank * COLS;

    const float* kb = keys   + (size_t)b * S * D_DIM + c0;
    const float* vb = values + (size_t)b * S * D_DIM + c0;

    float* sq4   = (float*)(sm + OFF_SQ4);
    float* kshf  = (float*)(sm + OFF_KSH);
    float* vshf  = (float*)(sm + OFF_VSH);
    float* recvf = (float*)(sm + OFF_RECV);
    float* cent  = (float*)(sm + OFF_CENT);
    float* stat  = (float*)(sm + OFF_STAT);

    // ---- init ----
    for (int i = tid; i < M_ST * COLS; i += TPB) { cent[i] = 0.0f; stat[i] = 0.0f; }
    for (int i = tid; i < 2 * 8 * 68; i += TPB) recvf[i] = 0.0f;
    if (tid < 4) sq4[tid] = 0.0f;
    if (tid == 0) {
        mbar_init(sbase + OFF_MBAR + 0, 7);   // one aggregated arrive per peer
        mbar_init(sbase + OFF_MBAR + 8, 7);
    }
    // load token 0 into buffer 0
    if (tid < 128) kshf[tid] = kb[tid];
    else           vshf[tid - 128] = vb[tid - 128];
    __syncthreads();
    cluster_sync_all();   // peers' mbarriers ready before any DSMEM traffic

    // ---- per-warp redundant decision state (identical across all warps/CTAs) ----
    int   K_reg = 0, psl = -1;
    float cnt0 = 0.0f, cnt1 = 0.0f;      // counts[lane], counts[lane+32]
    float cn2a = 0.0f, cn2b = 0.0f;      // cn2[lane],    cn2[lane+32]

    for (int t = 0; t < S; ++t) {
        const int buf = t & 1;

        // prefetch token t+1 from global (consumed in stage E)
        float pnx = 0.0f;
        if (t + 1 < S)
            pnx = (tid < 128) ? kb[(size_t)(t + 1) * D_DIM + tid]
                              : vb[(size_t)(t + 1) * D_DIM + (tid - 128)];

        // ---- stage B: partial dots over owned 128 cols + DSMEM all-gather ----
        {
            const float4 kq = ((const float4*)(kshf + buf * 128))[lane];
            float p[8];
            #pragma unroll
            for (int i = 0; i < 8; ++i) {
                const float4 c4 = *((const float4*)(cent + (wid * 8 + i) * COLS) + lane);
                p[i] = kq.x * c4.x + kq.y * c4.y + kq.z * c4.z + kq.w * c4.w;
            }
            #pragma unroll
            for (int off = 16; off; off >>= 1) {
                #pragma unroll
                for (int i = 0; i < 8; ++i)
                    p[i] += __shfl_xor_sync(0xffffffffu, p[i], off);
            }
            float p8 = 0.0f;
            if (wid == 0) {
                p8 = kq.x * kq.x + kq.y * kq.y + kq.z * kq.z + kq.w * kq.w;
                #pragma unroll
                for (int off = 16; off; off >>= 1)
                    p8 += __shfl_xor_sync(0xffffffffu, p8, off);
            }
            if (lane < 8) {          // lane r ships this warp's partials to CTA r
                const int r = lane;
                float sqs = 0.0f;
                if (wid == 0) sqs = sq4[0] + sq4[1] + sq4[2] + sq4[3];
                const int bidx = buf * 544 + rank * 68 + wid * 8;
                if (r == rank) {
                    float* dst = recvf + bidx;
                    #pragma unroll
                    for (int i = 0; i < 8; ++i) dst[i] = p[i];
                    if (wid == 0) { dst[64] = p8; dst[65] = sqs; }
                } else {
                    const uint32_t ra =
                        mapa_rank(sbase + OFF_RECV + (uint32_t)(bidx * 4), (uint32_t)r);
                    #pragma unroll
                    for (int i = 0; i < 8; ++i) st_dsmem(ra + 4u * i, p[i]);
                    if (wid == 0) { st_dsmem(ra + 256u, p8); st_dsmem(ra + 260u, sqs); }
                }
            }
        }
        __syncthreads();   // all local+remote stores issued; local recv visible

        // ---- aggregated arrival: ONE arrive per peer, 7 distinct mbarriers ----
        if (tid < 7) {
            asm volatile("fence.acq_rel.cluster;" ::: "memory");
            const int r = tid + (tid >= rank ? 1 : 0);
            mbar_arrive_remote(sbase + OFF_MBAR + (uint32_t)(buf * 8), (uint32_t)r);
        }
        mbar_wait_cluster(sbase + OFF_MBAR + (uint32_t)(buf * 8),
                          (uint32_t)((t >> 1) & 1));

        // ---- stage D: every warp computes the identical decision ----
        int slot, create;
        float denom;
        {
            const float* rcv = recvf + buf * 544;
            float s64 = 0.0f, s65 = 0.0f;
            #pragma unroll
            for (int r = 0; r < 8; ++r) {
                s64 += rcv[r * 68 + 64];
                s65 += rcv[r * 68 + 65];
            }
            // exact ||centroid||^2 refresh for the row updated last token
            if (psl >= 0) {
                if ((psl & 31) == lane) { if (psl < 32) cn2a = s65; else cn2b = s65; }
            }
            float d1 = 0.0f, d2 = 0.0f;
            #pragma unroll
            for (int r = 0; r < 8; ++r) {
                d1 += rcv[r * 68 + lane];
                d2 += rcv[r * 68 + 32 + lane];
            }
            const float rk = rsqrtf(s64 + EPS_F);
            const float v1 = (cnt0 > 0.0f) ? d1 * rsqrtf(cn2a + EPS_F) * rk : -3.0e38f;
            const float v2 = (cnt1 > 0.0f) ? d2 * rsqrtf(cn2b + EPS_F) * rk : -3.0e38f;
            float bv; int bi;
            if (v2 > v1) { bv = v2; bi = lane + 32; } else { bv = v1; bi = lane; }
            #pragma unroll
            for (int off = 16; off; off >>= 1) {   // argmax, first-index tiebreak
                const float ov = __shfl_xor_sync(0xffffffffu, bv, off);
                const int   oi = __shfl_xor_sync(0xffffffffu, bi, off);
                if (ov > bv || (ov == bv && oi < bi)) { bv = ov; bi = oi; }
            }
            create = (K_reg == 0) || (bv < THRESH_F && K_reg < M_ST);
            slot = create ? K_reg : bi;
            const float npre = (slot < 32)
                ? __shfl_sync(0xffffffffu, cnt0, slot)
                : __shfl_sync(0xffffffffu, cnt1, slot - 32);
            denom = npre + 1.0f;
            if (slot == lane)      cnt0 = create ? 1.0f : denom;
            if (slot == lane + 32) cnt1 = create ? 1.0f : denom;
            K_reg += create;
            psl = slot;
        }

        // ---- stage E: update owned slice + publish token t+1 ----
        if (tid < 128) {
            const float c = cent[slot * COLS + tid];
            const float k = kshf[buf * 128 + tid];
            const float nc = create ? k : (c + (k - c) / denom);
            cent[slot * COLS + tid] = nc;
            float sq = nc * nc;
            #pragma unroll
            for (int off = 16; off; off >>= 1)
                sq += __shfl_xor_sync(0xffffffffu, sq, off);
            if (lane == 0) sq4[wid] = sq;
            kshf[(buf ^ 1) * 128 + tid] = pnx;
        } else {
            const int j = tid - 128;
            const float s = stat[slot * COLS + j];
            const float v = vshf[buf * 128 + j];
            stat[slot * COLS + j] = create ? v : (s + (v - s) / denom);
            vshf[(buf ^ 1) * 128 + j] = pnx;
        }
        __syncthreads();   // E writes (cent/sq4/kshf/vshf) visible to next B
    }

    // ---- flush states ----
    {
        const int half = tid >> 7;
        const int j = tid & 127;
        float* ob = out + (size_t)b * M_ST * D_DIM + c0;
        for (int s = half * 32; s < half * 32 + 32; ++s)
            ob[(size_t)s * D_DIM + j] = stat[s * COLS + j];
    }
    cluster_sync_all();   // keep SMEM alive until peers' remote ops settle
}

extern "C" void kernel_launch(void* const* d_in, const int* in_sizes, int n_in,
                              void* d_out, int out_size) {
    const float* keys   = (const float*)d_in[0];
    const float* values = (const float*)d_in[1];
    float* out = (float*)d_out;

    const int B = out_size / (M_ST * D_DIM);
    const int S = in_sizes[0] / (B * D_DIM);

    cudaFuncSetAttribute(sparse_agg_kernel,
                         cudaFuncAttributeMaxDynamicSharedMemorySize, SMEM_BYTES);
    sparse_agg_kernel<<<B * RANKS, TPB, SMEM_BYTES>>>(keys, values, out, S);
}

// round 12
// speedup vs baseline: 2.4091x; 2.4091x over previous
#include <cuda_runtime.h>
#include <cstdint>

// SparseStateAggregator, block-parallel (T=8): ONE cluster exchange per 8 tokens.
// Dots of block m+1 vs C_{m-1} are computed and shipped during iteration m; block
// m+1's decisions correct those dots for block m's 8 rank-1 updates (and its own
// intra-block updates) via a precomputed key Gram matrix. Exact post-block row
// norms ship with the same exchange.

#define D_DIM   1024
#define M_ST    64
#define RANKS   8
#define COLS    128
#define CP      132      // padded row stride (floats)
#define T       8
#define TPB     256
#define THRESH_F 0.9f
#define EPS_F   1e-12f
#define NSHIP   520      // 512 dot partials + 8 row-norm partials

#define OFF_MBAR 0
#define OFF_GSH  32       // 128 floats: Gram of current block
#define OFF_SUM  544      // 520 floats: rank-summed partials
#define OFF_KBUF 2624     // 2 x 8 x 132 floats
#define OFF_VBUF 11072    // 2 x 8 x 128 floats
#define OFF_RECV 19264    // 4 x 8 x 520 floats
#define OFF_CENT 85824    // 64 x 132 floats
#define OFF_STAT 119616   // 64 x 132 floats
#define SMEM_BYTES 153408

__device__ float g_gram[8 * 512 * 128];   // [b*NB+m][j*16+i]

static __device__ __forceinline__ uint32_t smem_u32(const void* p) {
    uint32_t a;
    asm("{ .reg .u64 t; cvta.to.shared.u64 t, %1; cvt.u32.u64 %0, t; }" : "=r"(a) : "l"(p));
    return a;
}
static __device__ __forceinline__ uint32_t mapa_rank(uint32_t addr, uint32_t rank) {
    uint32_t ra;
    asm("mapa.shared::cluster.u32 %0, %1, %2;" : "=r"(ra) : "r"(addr), "r"(rank));
    return ra;
}
static __device__ __forceinline__ void st_dsmem(uint32_t addr, float v) {
    asm volatile("st.shared::cluster.f32 [%0], %1;" :: "r"(addr), "f"(v) : "memory");
}
static __device__ __forceinline__ void mbar_init(uint32_t addr, uint32_t cnt) {
    asm volatile("mbarrier.init.shared.b64 [%0], %1;" :: "r"(addr), "r"(cnt) : "memory");
}
static __device__ __forceinline__ void mbar_arrive_remote(uint32_t local_mbar, uint32_t rank) {
    uint32_t ra = mapa_rank(local_mbar, rank);
    asm volatile("mbarrier.arrive.release.cluster.shared::cluster.b64 _, [%0];"
                 :: "r"(ra) : "memory");
}
static __device__ __forceinline__ void mbar_wait_cluster(uint32_t mbar, uint32_t parity) {
    asm volatile(
        "{\n\t.reg .pred P1;\n\t"
        "LAB_WAIT_%=:\n\t"
        "mbarrier.try_wait.parity.acquire.cluster.shared::cta.b64 P1, [%0], %1;\n\t"
        "@!P1 bra LAB_WAIT_%=;\n\t}\n"
        :: "r"(mbar), "r"(parity) : "memory");
}
static __device__ __forceinline__ void cluster_sync_all() {
    asm volatile("barrier.cluster.arrive.aligned;" ::: "memory");
    asm volatile("barrier.cluster.wait.aligned;" ::: "memory");
}
static __device__ __forceinline__ unsigned om(float f) {     // order-preserving float->u32
    unsigned u = __float_as_uint(f);
    return ((int)u < 0) ? ~u : (u | 0x80000000u);
}
static __device__ __forceinline__ float unom(unsigned u) {
    return ((int)u < 0) ? __uint_as_float(u & 0x7fffffffu) : __uint_as_float(~u);
}
static __device__ __forceinline__ unsigned redux_max_u32(unsigned v) {
    unsigned r;
    asm("redux.sync.max.u32 %0, %1, 0xffffffff;" : "=r"(r) : "r"(v));
    return r;
}
static __device__ __forceinline__ void ffma2(float2& acc, float2 a, float2 b) {
    unsigned long long au = *reinterpret_cast<const unsigned long long*>(&a);
    unsigned long long bu = *reinterpret_cast<const unsigned long long*>(&b);
    unsigned long long cu = *reinterpret_cast<unsigned long long*>(&acc);
    asm("fma.rn.f32x2 %0, %1, %2, %0;" : "+l"(cu) : "l"(au), "l"(bu));
    *reinterpret_cast<unsigned long long*>(&acc) = cu;
}

// ---- Gram precompute: G[b,m][j*16+i] = dot(k_{mT+j}, k_{(m-1)T+i}) for i<8,
//      dot(k_{mT+j}, k_{mT+i-8}) for i>=8 (full 1024-dim). One block per (b,m). ----
__global__ void __launch_bounds__(256) gram_kernel(const float* __restrict__ keys,
                                                   int S, int NB) {
    const int blk = blockIdx.x;
    const int m = blk % NB, b = blk / NB;
    const int j = threadIdx.x >> 5, lane = threadIdx.x & 31;
    const float4* kj = (const float4*)(keys + ((size_t)b * S + m * T + j) * D_DIM);
    float4 a[8];
    #pragma unroll
    for (int s = 0; s < 8; ++s) a[s] = kj[s * 32 + lane];
    #pragma unroll
    for (int i = 0; i < 16; ++i) {
        const int ti = (i < 8) ? ((m - 1) * T + i) : (m * T + i - 8);
        float g = 0.0f;
        if (ti >= 0) {
            const float4* kc = (const float4*)(keys + ((size_t)b * S + ti) * D_DIM);
            #pragma unroll
            for (int s = 0; s < 8; ++s) {
                const float4 c = kc[s * 32 + lane];
                g += a[s].x * c.x + a[s].y * c.y + a[s].z * c.z + a[s].w * c.w;
            }
            #pragma unroll
            for (int off = 16; off; off >>= 1)
                g += __shfl_xor_sync(0xffffffffu, g, off);
        }
        if (lane == 0) g_gram[(size_t)blk * 128 + j * 16 + i] = g;
    }
}

__global__ void __cluster_dims__(RANKS, 1, 1) __launch_bounds__(TPB, 1)
sparse_agg_kernel(const float* __restrict__ keys,
                  const float* __restrict__ values,
                  float* __restrict__ out, int S, int NB)
{
    extern __shared__ unsigned char sm[];
    const uint32_t sbase = smem_u32(sm);

    const int tid  = threadIdx.x;
    const int wid  = tid >> 5;
    const int lane = tid & 31;
    const int rank = blockIdx.x & (RANKS - 1);
    const int b    = blockIdx.x >> 3;
    const int c0   = rank * COLS;

    const float* kb = keys   + (size_t)b * S * D_DIM + c0;
    const float* vb = values + (size_t)b * S * D_DIM + c0;

    float* gsh   = (float*)(sm + OFF_GSH);
    float* summed= (float*)(sm + OFF_SUM);
    float* kbuf  = (float*)(sm + OFF_KBUF);
    float* vbuf  = (float*)(sm + OFF_VBUF);
    float* recvf = (float*)(sm + OFF_RECV);
    float* cent  = (float*)(sm + OFF_CENT);
    float* stat  = (float*)(sm + OFF_STAT);

    // ---- init ----
    for (int i = tid; i < M_ST * CP; i += TPB) { cent[i] = 0.0f; stat[i] = 0.0f; }
    for (int i = tid; i < 4 * RANKS * NSHIP; i += TPB) recvf[i] = 0.0f;
    if (tid == 0) {
        #pragma unroll
        for (int i = 0; i < 4; ++i) mbar_init(sbase + OFF_MBAR + 8u * i, 7);
    }
    // preload blocks 0,1 into kbuf/vbuf
    {
        const int e = tid * 4, i = e >> 7, c = e & 127;
        #pragma unroll
        for (int blk = 0; blk < 2; ++blk) if (blk < NB) {
            const float4 kv = *(const float4*)(kb + (size_t)(blk * T + i) * D_DIM + c);
            const float4 vv = *(const float4*)(vb + (size_t)(blk * T + i) * D_DIM + c);
            *(float4*)(kbuf + blk * T * CP + i * CP + c) = kv;
            *(float4*)(vbuf + blk * T * COLS + i * COLS + c) = vv;
        }
    }
    __syncthreads();
    cluster_sync_all();
    // pre-arrive for block 0 (recv zeroed: dots/norms vs empty centroids = 0)
    if (tid < 7) {
        const int r = tid + (tid >= rank ? 1 : 0);
        mbar_arrive_remote(sbase + OFF_MBAR, (uint32_t)r);
    }

    // ---- per-lane persistent state (bit-identical across warps/CTAs) ----
    int   K_reg = 0;
    float cnt0 = 0.0f, cnt1 = 0.0f;    // counts[lane], counts[lane+32]
    float cn2a = 0.0f, cn2b = 0.0f;    // ||centroid||^2
    int   pw[T];                        // slot | create<<8 (prev block)
    float pinv[T], dens[T];
    #pragma unroll
    for (int i = 0; i < T; ++i) { pw[i] = -1; pinv[i] = 0.0f; dens[i] = 1.0f; }

    const int jtok = tid & 7;           // B-stage token
    const int r1 = tid >> 3, r2 = r1 + 32;

    for (int m = 0; m < NB; ++m) {
        const float greg = (tid < 128) ? g_gram[(size_t)(b * NB + m) * 128 + tid] : 0.0f;
        float4 kpre = make_float4(0, 0, 0, 0), vpre = kpre;
        if (m + 2 < NB) {
            const int e = tid * 4, i = e >> 7, c = e & 127;
            kpre = *(const float4*)(kb + (size_t)((m + 2) * T + i) * D_DIM + c);
            vpre = *(const float4*)(vb + (size_t)((m + 2) * T + i) * D_DIM + c);
        }

        // ---- B: dots of block m+1 vs current centroids, ship to all ranks ----
        if (m + 1 < NB) {
            const float4* kp = (const float4*)(kbuf + ((m + 1) & 1) * T * CP + jtok * CP);
            const float4* cA = (const float4*)(cent + r1 * CP);
            const float4* cB = (const float4*)(cent + r2 * CP);
            float2 a1 = make_float2(0, 0), a2 = a1;
            #pragma unroll
            for (int s = 0; s < 32; ++s) {
                const float4 k4 = kp[s], c1 = cA[s], c2 = cB[s];
                ffma2(a1, make_float2(c1.x, c1.y), make_float2(k4.x, k4.y));
                ffma2(a1, make_float2(c1.z, c1.w), make_float2(k4.z, k4.w));
                ffma2(a2, make_float2(c2.x, c2.y), make_float2(k4.x, k4.y));
                ffma2(a2, make_float2(c2.z, c2.w), make_float2(k4.z, k4.w));
            }
            const float d1 = a1.x + a1.y, d2 = a2.x + a2.y;
            const uint32_t l1 = sbase + OFF_RECV +
                (uint32_t)(((((m + 1) & 3) * RANKS + rank) * NSHIP + jtok * 64 + r1) * 4);
            #pragma unroll
            for (int r = 0; r < RANKS; ++r) {
                const uint32_t ra = mapa_rank(l1, (uint32_t)r);
                st_dsmem(ra, d1);
                st_dsmem(ra + 128u, d2);
            }
        }

        // ---- wait for block m data (arrived at end of previous iteration) ----
        mbar_wait_cluster(sbase + OFF_MBAR + (uint32_t)((m & 3) * 8),
                          (uint32_t)((m >> 2) & 1));

        // ---- C: reduce rank partials (fixed order -> bit-identical everywhere) ----
        {
            const float* rv = recvf + (m & 3) * RANKS * NSHIP;
            float s0 = 0.0f, s1 = 0.0f;
            #pragma unroll
            for (int r = 0; r < RANKS; ++r) {
                s0 += rv[r * NSHIP + tid];
                s1 += rv[r * NSHIP + 256 + tid];
            }
            summed[tid] = s0;
            summed[256 + tid] = s1;
            if (tid < 8) {
                float s2 = 0.0f;
                #pragma unroll
                for (int r = 0; r < RANKS; ++r) s2 += rv[r * NSHIP + 512 + tid];
                summed[512 + tid] = s2;
            }
            if (tid < 128) gsh[tid] = greg;
        }
        __syncthreads();

        // ---- D: all warps redundantly decide the 8 tokens of block m ----
        {
            float da[T], db[T];
            #pragma unroll
            for (int j = 0; j < T; ++j) {
                da[j] = summed[j * 64 + lane];
                db[j] = summed[j * 64 + 32 + lane];
            }
            // refresh exact norms + correct dots for prev block's 8 updates (in order)
            #pragma unroll
            for (int i = 0; i < T; ++i) {
                const int w = pw[i];
                if (w >= 0) {
                    const int ps = w & 63, pc = w >> 8;
                    const float pv = pinv[i], pa = 1.0f - pv;
                    if (ps < 32) {
                        if (lane == ps) {
                            cn2a = summed[512 + i];
                            #pragma unroll
                            for (int j = 0; j < T; ++j) {
                                const float g = gsh[j * 16 + i];
                                da[j] = pc ? g : pa * da[j] + pv * g;
                            }
                        }
                    } else {
                        if (lane == ps - 32) {
                            cn2b = summed[512 + i];
                            #pragma unroll
                            for (int j = 0; j < T; ++j) {
                                const float g = gsh[j * 16 + i];
                                db[j] = pc ? g : pa * db[j] + pv * g;
                            }
                        }
                    }
                }
            }
            // sequential decisions with intra-block corrections
            #pragma unroll
            for (int j = 0; j < T; ++j) {
                const float kn2 = gsh[j * 16 + 8 + j];
                const float rk = rsqrtf(kn2 + EPS_F);
                const float v1 = (cnt0 > 0.0f) ? da[j] * rsqrtf(cn2a + EPS_F) * rk : -3.0e38f;
                const float v2 = (cnt1 > 0.0f) ? db[j] * rsqrtf(cn2b + EPS_F) * rk : -3.0e38f;
                const unsigned u1 = om(v1), u2 = om(v2);
                const unsigned gm = redux_max_u32(u1 > u2 ? u1 : u2);
                const unsigned b1 = __ballot_sync(0xffffffffu, u1 == gm);
                const unsigned b2 = __ballot_sync(0xffffffffu, u2 == gm);
                const int bi = b1 ? (__ffs(b1) - 1) : (32 + __ffs(b2) - 1);
                const float bv = unom(gm);
                const int create = (K_reg == 0) || (bv < THRESH_F && K_reg < M_ST);
                const int slot = create ? K_reg : bi;
                const int sl = slot & 31;
                const float c0s = __shfl_sync(0xffffffffu, cnt0, sl);
                const float c1s = __shfl_sync(0xffffffffu, cnt1, sl);
                const float denom = ((slot < 32) ? c0s : c1s) + 1.0f;
                const float inv = 1.0f / denom, aa = 1.0f - inv;
                if (lane == sl) {
                    if (slot < 32) {
                        cnt0 = create ? 1.0f : denom;
                        cn2a = create ? kn2
                             : aa * aa * cn2a + 2.0f * aa * inv * da[j] + inv * inv * kn2;
                    } else {
                        cnt1 = create ? 1.0f : denom;
                        cn2b = create ? kn2
                             : aa * aa * cn2b + 2.0f * aa * inv * db[j] + inv * inv * kn2;
                    }
                }
                #pragma unroll
                for (int jj = j + 1; jj < T; ++jj) {
                    const float g = gsh[jj * 16 + 8 + j];
                    if (lane == sl) {
                        if (slot < 32) da[jj] = create ? g : aa * da[jj] + inv * g;
                        else           db[jj] = create ? g : aa * db[jj] + inv * g;
                    }
                }
                K_reg += create;
                pw[j] = slot | (create << 8);
                pinv[j] = inv;
                dens[j] = denom;
            }
        }

        // ---- E: apply 8 updates (reference-exact form) ----
        if (tid < 128) {
            #pragma unroll
            for (int j = 0; j < T; ++j) {
                const int slot = pw[j] & 63, create = pw[j] >> 8;
                float* cp = cent + slot * CP + tid;
                const float k = kbuf[(m & 1) * T * CP + j * CP + tid];
                const float c = *cp;
                *cp = create ? k : c + (k - c) / dens[j];
            }
        } else {
            const int col = tid - 128;
            #pragma unroll
            for (int j = 0; j < T; ++j) {
                const int slot = pw[j] & 63, create = pw[j] >> 8;
                float* sp = stat + slot * CP + col;
                const float v = vbuf[(m & 1) * T * COLS + j * COLS + col];
                const float s = *sp;
                *sp = create ? v : s + (v - s) / dens[j];
            }
        }
        __syncthreads();

        // ---- E2: exact post-block row norms (warp w -> update w) + ship ----
        if (m + 1 < NB) {
            int myslot = 0;
            #pragma unroll
            for (int j = 0; j < T; ++j) if (wid == j) myslot = pw[j] & 63;
            const float4 c4 = ((const float4*)(cent + myslot * CP))[lane];
            float sq = c4.x * c4.x + c4.y * c4.y + c4.z * c4.z + c4.w * c4.w;
            #pragma unroll
            for (int off = 16; off; off >>= 1)
                sq += __shfl_xor_sync(0xffffffffu, sq, off);
            if (lane < 8) {
                const uint32_t loff = sbase + OFF_RECV +
                    (uint32_t)(((((m + 1) & 3) * RANKS + rank) * NSHIP + 512 + wid) * 4);
                st_dsmem(mapa_rank(loff, (uint32_t)lane), sq);
            }
        }
        // store prefetched block m+2 (kbuf[m&1] reads finished before sync above)
        if (m + 2 < NB) {
            const int e = tid * 4, i = e >> 7, c = e & 127;
            *(float4*)(kbuf + (m & 1) * T * CP + i * CP + c) = kpre;
            *(float4*)(vbuf + (m & 1) * T * COLS + i * COLS + c) = vpre;
        }
        __syncthreads();   // all DSMEM stores issued; kbuf ready for next B

        if (m + 1 < NB && tid < 7) {
            asm volatile("fence.acq_rel.cluster;" ::: "memory");
            const int r = tid + (tid >= rank ? 1 : 0);
            mbar_arrive_remote(sbase + OFF_MBAR + (uint32_t)(((m + 1) & 3) * 8), (uint32_t)r);
        }
    }

    // ---- flush states ----
    {
        const int half = tid >> 7, j = tid & 127;
        float* ob = out + (size_t)b * M_ST * D_DIM + c0;
        for (int s = half * 32; s < half * 32 + 32; ++s)
            ob[(size_t)s * D_DIM + j] = stat[s * CP + j];
    }
    cluster_sync_all();   // keep SMEM alive until peers' remote ops settle
}

extern "C" void kernel_launch(void* const* d_in, const int* in_sizes, int n_in,
                              void* d_out, int out_size) {
    const float* keys   = (const float*)d_in[0];
    const float* values = (const float*)d_in[1];
    float* out = (float*)d_out;

    const int B = out_size / (M_ST * D_DIM);
    const int S = in_sizes[0] / (B * D_DIM);
    const int NB = S / T;

    gram_kernel<<<B * NB, 256>>>(keys, S, NB);

    cudaFuncSetAttribute(sparse_agg_kernel,
                         cudaFuncAttributeMaxDynamicSharedMemorySize, SMEM_BYTES);
    sparse_agg_kernel<<<B * RANKS, TPB, SMEM_BYTES>>>(keys, values, out, S, NB);
}